// round 15
// baseline (speedup 1.0000x reference)
#include <cuda_runtime.h>
#include <cuda_bf16.h>
#include <cstdint>

#define N_NODES 50000
#define N_EDGES 800000
#define D 128
#define K2 256
#define SCAN_BLOCKS 49   // ceil(50000/1024)

// ---------------- scratch (no allocations allowed) ----------------
__device__ __align__(16) float g_h0 [N_NODES * D];
__device__ __align__(16) float g_h1 [N_NODES * D];
__device__ __align__(16) __nv_bfloat16 g_Wbh[4][D * K2]; // [j][k] K-major, hi
__device__ __align__(16) __nv_bfloat16 g_Wbl[4][D * K2]; // lo
__device__ int   g_deg[N_NODES];
__device__ int   g_rowptr[N_NODES + 1];
__device__ int   g_cursor[N_NODES];
__device__ int   g_eid[N_EDGES];
__device__ int   g_es[N_EDGES];
__device__ int   g_ed[N_EDGES];
__device__ int   g_bsum[SCAN_BLOCKS];
__device__ int   g_is64;

// ---------------- helpers ----------------
__device__ __forceinline__ uint32_t smem_to_u32(const void* p) {
    uint32_t a;
    asm("{ .reg .u64 t; cvta.to.shared.u64 t, %1; cvt.u32.u64 %0, t; }" : "=r"(a) : "l"(p));
    return a;
}
#define SMEM_SWIZZLE_128B(o) ((o) ^ (((o) >> 3) & 0x70))

#define LDMATRIX_X4(r0, r1, r2, r3, addr) \
    asm volatile("ldmatrix.sync.aligned.m8n8.x4.shared.b16 {%0,%1,%2,%3}, [%4];" \
                 : "=r"(r0), "=r"(r1), "=r"(r2), "=r"(r3) : "r"(addr))

#define MMA_BF16(d0, d1, d2, d3, a0, a1, a2, a3, b0, b1) \
    asm volatile("mma.sync.aligned.m16n8k16.row.col.f32.bf16.bf16.f32 " \
                 "{%0,%1,%2,%3}, {%4,%5,%6,%7}, {%8,%9}, {%0,%1,%2,%3};" \
                 : "+f"(d0), "+f"(d1), "+f"(d2), "+f"(d3) \
                 : "r"(a0), "r"(a1), "r"(a2), "r"(a3), "r"(b0), "r"(b1))

#define NB_SYNC(id, cnt)   asm volatile("bar.sync %0, %1;"   :: "r"(id), "r"(cnt) : "memory")
#define NB_ARRIVE(id, cnt) asm volatile("bar.arrive %0, %1;" :: "r"(id), "r"(cnt) : "memory")

__device__ __forceinline__ uint2 pack_hi_lo_hi(float4 v) {
    __nv_bfloat16 h0 = __float2bfloat16(v.x), h1 = __float2bfloat16(v.y);
    __nv_bfloat16 h2 = __float2bfloat16(v.z), h3 = __float2bfloat16(v.w);
    uint2 p;
    p.x = ((uint32_t)__bfloat16_as_ushort(h1) << 16) | __bfloat16_as_ushort(h0);
    p.y = ((uint32_t)__bfloat16_as_ushort(h3) << 16) | __bfloat16_as_ushort(h2);
    return p;
}
__device__ __forceinline__ uint2 pack_hi_lo_lo(float4 v) {
    __nv_bfloat16 h0 = __float2bfloat16(v.x), h1 = __float2bfloat16(v.y);
    __nv_bfloat16 h2 = __float2bfloat16(v.z), h3 = __float2bfloat16(v.w);
    __nv_bfloat16 l0 = __float2bfloat16(v.x - __bfloat162float(h0));
    __nv_bfloat16 l1 = __float2bfloat16(v.y - __bfloat162float(h1));
    __nv_bfloat16 l2 = __float2bfloat16(v.z - __bfloat162float(h2));
    __nv_bfloat16 l3 = __float2bfloat16(v.w - __bfloat162float(h3));
    uint2 p;
    p.x = ((uint32_t)__bfloat16_as_ushort(l1) << 16) | __bfloat16_as_ushort(l0);
    p.y = ((uint32_t)__bfloat16_as_ushort(l3) << 16) | __bfloat16_as_ushort(l2);
    return p;
}

// ---------------- dtype detection + decode(+count) ----------------
__global__ void detect_kernel(const int* __restrict__ e32) {
    bool z = (e32[2 * threadIdx.x + 1] == 0);
    unsigned m = __ballot_sync(0xffffffffu, z);
    if (threadIdx.x == 0) g_is64 = (m == 0xffffffffu) ? 1 : 0;
}

__global__ void zero_deg_kernel() {
    int i = blockIdx.x * blockDim.x + threadIdx.x;
    if (i < N_NODES) g_deg[i] = 0;
}

__global__ void decode_count_kernel(const int* __restrict__ e32) {
    int i = blockIdx.x * blockDim.x + threadIdx.x;
    if (i >= 2 * N_EDGES) return;
    int v = g_is64 ? e32[2 * i] : e32[i];
    v = min(max(v, 0), N_NODES - 1);
    if (i < N_EDGES) {
        g_es[i] = v;
    } else {
        g_ed[i - N_EDGES] = v;
        atomicAdd(&g_deg[v], 1);
    }
}

// ---------------- CSR scans ----------------
__global__ void scan1_kernel() {
    __shared__ int wsum[32];
    int i = blockIdx.x * 1024 + threadIdx.x;
    int lane = threadIdx.x & 31, wrp = threadIdx.x >> 5;
    int v = (i < N_NODES) ? g_deg[i] : 0;
    int x = v;
#pragma unroll
    for (int off = 1; off < 32; off <<= 1) {
        int y = __shfl_up_sync(0xffffffffu, x, off);
        if (lane >= off) x += y;
    }
    if (lane == 31) wsum[wrp] = x;
    __syncthreads();
    if (wrp == 0) {
        int s = wsum[lane];
#pragma unroll
        for (int off = 1; off < 32; off <<= 1) {
            int y = __shfl_up_sync(0xffffffffu, s, off);
            if (lane >= off) s += y;
        }
        wsum[lane] = s;
    }
    __syncthreads();
    int incl = x + (wrp > 0 ? wsum[wrp - 1] : 0);
    if (i < N_NODES) g_rowptr[i] = incl - v;
    if (threadIdx.x == 1023) g_bsum[blockIdx.x] = incl;
}

__global__ void scan2_kernel() {
    __shared__ int ws[2];
    int t = threadIdx.x;
    int lane = t & 31, wrp = t >> 5;
    int v = (t < SCAN_BLOCKS) ? g_bsum[t] : 0;
    int x = v;
#pragma unroll
    for (int off = 1; off < 32; off <<= 1) {
        int y = __shfl_up_sync(0xffffffffu, x, off);
        if (lane >= off) x += y;
    }
    if (lane == 31) ws[wrp] = x;
    __syncthreads();
    int excl = x - v + (wrp == 1 ? ws[0] : 0);
    if (t < SCAN_BLOCKS) g_bsum[t] = excl;
}

__global__ void scan3_kernel() {
    int i = blockIdx.x * 1024 + threadIdx.x;
    if (i < N_NODES) {
        int v = g_rowptr[i] + g_bsum[blockIdx.x];
        g_rowptr[i] = v;
        g_cursor[i] = v;
    }
    if (i == 0) g_rowptr[N_NODES] = N_EDGES;
}

__global__ void fill_kernel() {
    int e = blockIdx.x * blockDim.x + threadIdx.x;
    if (e < N_EDGES) {
        int pos = atomicAdd(&g_cursor[g_ed[e]], 1);
        g_eid[pos] = g_es[e];
    }
}

// ---------------- build bf16 hi/lo weights, all 4 layers in one launch -------
struct WPtrs { const float* wl[4]; const float* wr[4]; };
__global__ void buildWb_kernel(WPtrs wp) {
    int idx = blockIdx.x * blockDim.x + threadIdx.x;
    if (idx < 4 * D * K2) {
        int layer = idx >> 15;           // / (D*K2=32768)
        int rem = idx & 32767;
        int j = rem >> 8;
        int k = rem & 255;
        float w = (k < D) ? wp.wl[layer][j * D + k] : wp.wr[layer][j * D + (k - D)];
        __nv_bfloat16 hi = __float2bfloat16(w);
        __nv_bfloat16 lo = __float2bfloat16(w - __bfloat162float(hi));
        g_Wbh[layer][rem] = hi;
        g_Wbl[layer][rem] = lo;
    }
}

// ---------------- warp-specialized fused layer -------------------------------
// 512 thr: warps 0-7 producers (gather+convert A chunks into 3-slot ring),
//          warps 8-15 consumers (B-resident HMMA + epilogue).
// smem: slots 0..2 @ s*32768 (hi @ +0, lo @ +16384); B @ 98304, 4 chunks of
//       32768 (hi @ +0, lo @ +16384). Total 229376 B -> 1 CTA/SM.
#define SLOT_BASE(s) ((uint32_t)(s) * 32768u)
#define B_BASE 98304u
#define SMEM_TOT 229376
#define NBT 512

__global__ void __launch_bounds__(512, 1)
fused_layer_kernel(const float* __restrict__ hin, int layer,
                   const float* __restrict__ bias, float* __restrict__ out, int relu) {
    extern __shared__ char smem[];
    const uint32_t smem_base = smem_to_u32(smem);
    const int tid  = threadIdx.x;
    const int wid  = tid >> 5;
    const int lane = tid & 31;
    const int row0 = blockIdx.x * 128;

    if (wid < 8) {
        // ================= PRODUCER =================
        // chunks 0,1: gather means (slots 0,1). lanes 0-15 -> chunk0, 16-31 -> chunk1.
        const int pw = wid;
        for (int nn = 0; nn < 16; nn++) {
            int r = pw * 16 + nn;
            int node = row0 + r;
            float4 acc = make_float4(0.f, 0.f, 0.f, 0.f);
            if (node < N_NODES) {
                int beg = g_rowptr[node];
                int end = g_rowptr[node + 1];
                int i = beg;
                for (; i + 7 < end; i += 8) {
                    int s0 = __ldg(&g_eid[i]);     int s1 = __ldg(&g_eid[i + 1]);
                    int s2 = __ldg(&g_eid[i + 2]); int s3 = __ldg(&g_eid[i + 3]);
                    int s4 = __ldg(&g_eid[i + 4]); int s5 = __ldg(&g_eid[i + 5]);
                    int s6 = __ldg(&g_eid[i + 6]); int s7 = __ldg(&g_eid[i + 7]);
                    float4 v0 = *reinterpret_cast<const float4*>(hin + (size_t)s0 * D + lane * 4);
                    float4 v1 = *reinterpret_cast<const float4*>(hin + (size_t)s1 * D + lane * 4);
                    float4 v2 = *reinterpret_cast<const float4*>(hin + (size_t)s2 * D + lane * 4);
                    float4 v3 = *reinterpret_cast<const float4*>(hin + (size_t)s3 * D + lane * 4);
                    float4 v4 = *reinterpret_cast<const float4*>(hin + (size_t)s4 * D + lane * 4);
                    float4 v5 = *reinterpret_cast<const float4*>(hin + (size_t)s5 * D + lane * 4);
                    float4 v6 = *reinterpret_cast<const float4*>(hin + (size_t)s6 * D + lane * 4);
                    float4 v7 = *reinterpret_cast<const float4*>(hin + (size_t)s7 * D + lane * 4);
                    acc.x += (v0.x + v1.x) + (v2.x + v3.x) + (v4.x + v5.x) + (v6.x + v7.x);
                    acc.y += (v0.y + v1.y) + (v2.y + v3.y) + (v4.y + v5.y) + (v6.y + v7.y);
                    acc.z += (v0.z + v1.z) + (v2.z + v3.z) + (v4.z + v5.z) + (v6.z + v7.z);
                    acc.w += (v0.w + v1.w) + (v2.w + v3.w) + (v4.w + v5.w) + (v6.w + v7.w);
                }
                for (; i < end; i++) {
                    int s = __ldg(&g_eid[i]);
                    float4 v = *reinterpret_cast<const float4*>(hin + (size_t)s * D + lane * 4);
                    acc.x += v.x; acc.y += v.y; acc.z += v.z; acc.w += v.w;
                }
                float inv = 1.0f / (float)max(end - beg, 1);
                acc.x *= inv; acc.y *= inv; acc.z *= inv; acc.w *= inv;
            }
            uint32_t base = SLOT_BASE(lane >> 4);
            uint32_t sw = SMEM_SWIZZLE_128B((uint32_t)(r * 128 + (lane & 15) * 8));
            *reinterpret_cast<uint2*>(smem + base + sw)          = pack_hi_lo_hi(acc);
            *reinterpret_cast<uint2*>(smem + base + 16384 + sw)  = pack_hi_lo_lo(acc);
        }
        __threadfence_block();
        NB_ARRIVE(1, NBT);   // chunk0 full
        NB_ARRIVE(2, NBT);   // chunk1 full

        // chunk2: self features cols 0..63 -> slot 2
#pragma unroll
        for (int i = 0; i < 8; i++) {
            int idx = tid + i * 256;      // 0..2047
            int r  = idx >> 4;
            int c4 = idx & 15;
            int grow = row0 + r;
            float4 v = make_float4(0.f, 0.f, 0.f, 0.f);
            if (grow < N_NODES)
                v = *reinterpret_cast<const float4*>(hin + (size_t)grow * D + c4 * 4);
            uint32_t sw = SMEM_SWIZZLE_128B((uint32_t)(r * 128 + c4 * 8));
            *reinterpret_cast<uint2*>(smem + SLOT_BASE(2) + sw)         = pack_hi_lo_hi(v);
            *reinterpret_cast<uint2*>(smem + SLOT_BASE(2) + 16384 + sw) = pack_hi_lo_lo(v);
        }
        __threadfence_block();
        NB_ARRIVE(3, NBT);   // chunk2 full

        // chunk3: self features cols 64..127 -> slot 0 (wait until consumed)
        NB_SYNC(4, NBT);     // wait chunk0 consumed
#pragma unroll
        for (int i = 0; i < 8; i++) {
            int idx = tid + i * 256;
            int r  = idx >> 4;
            int c4 = idx & 15;
            int grow = row0 + r;
            float4 v = make_float4(0.f, 0.f, 0.f, 0.f);
            if (grow < N_NODES)
                v = *reinterpret_cast<const float4*>(hin + (size_t)grow * D + 64 + c4 * 4);
            uint32_t sw = SMEM_SWIZZLE_128B((uint32_t)(r * 128 + c4 * 8));
            *reinterpret_cast<uint2*>(smem + SLOT_BASE(0) + sw)         = pack_hi_lo_hi(v);
            *reinterpret_cast<uint2*>(smem + SLOT_BASE(0) + 16384 + sw) = pack_hi_lo_lo(v);
        }
        __threadfence_block();
        NB_ARRIVE(1, NBT);   // chunk3 full (slot 0, barrier 1 round 2)
    } else {
        // ================= CONSUMER =================
        const int ctid = tid - 256;        // 0..255
        const int cw = wid - 8;            // 0..7
        const int warp_m = (cw >> 2) * 64;
        const int warp_n = (cw & 3) * 32;
        const __nv_bfloat16* __restrict__ Bhp = g_Wbh[layer];
        const __nv_bfloat16* __restrict__ Blp = g_Wbl[layer];

        // load all 4 B chunks (hi+lo) once
#pragma unroll
        for (int c = 0; c < 4; c++) {
#pragma unroll
            for (int i = 0; i < 8; i++) {
                int idx = ctid + i * 256;
                int r  = idx >> 4;
                int c4 = idx & 15;
                int k = c * 64 + c4 * 4;
                uint2 vh = *reinterpret_cast<const uint2*>(Bhp + (size_t)r * K2 + k);
                uint2 vl = *reinterpret_cast<const uint2*>(Blp + (size_t)r * K2 + k);
                uint32_t sw = SMEM_SWIZZLE_128B((uint32_t)(r * 128 + c4 * 8));
                *reinterpret_cast<uint2*>(smem + B_BASE + c * 32768u + sw)          = vh;
                *reinterpret_cast<uint2*>(smem + B_BASE + c * 32768u + 16384u + sw) = vl;
            }
        }
        NB_SYNC(7, 256);    // B visible to all consumer warps

        float acc[4][4][4];
#pragma unroll
        for (int mt = 0; mt < 4; mt++)
#pragma unroll
            for (int nt = 0; nt < 4; nt++)
#pragma unroll
                for (int q = 0; q < 4; q++) acc[mt][nt][q] = 0.f;

        const int a_row  = (lane & 15);
        const int a_koff = (lane >> 4) * 8;
        const int b_row  = (lane & 7) + ((lane >> 4) << 3);
        const int b_koff = ((lane >> 3) & 1) * 8;

#pragma unroll
        for (int c = 0; c < 4; c++) {
            int slot = (c < 3) ? c : 0;
            NB_SYNC(1 + slot, NBT);      // wait chunk c full
            const uint32_t aBase = smem_base + SLOT_BASE(slot);
            const uint32_t bBase = smem_base + B_BASE + (uint32_t)c * 32768u;
#pragma unroll
            for (int ks = 0; ks < 4; ks++) {
                uint32_t bh[2][4], blo[2][4];
#pragma unroll
                for (int np = 0; np < 2; np++) {
                    uint32_t off = SMEM_SWIZZLE_128B(
                        (uint32_t)((warp_n + np * 16 + b_row) * 128 + (ks * 16 + b_koff) * 2));
                    LDMATRIX_X4(bh[np][0], bh[np][1], bh[np][2], bh[np][3], bBase + off);
                    LDMATRIX_X4(blo[np][0], blo[np][1], blo[np][2], blo[np][3],
                                bBase + 16384u + off);
                }
                uint32_t a[4][4];
#pragma unroll
                for (int mt = 0; mt < 4; mt++) {
                    uint32_t off = SMEM_SWIZZLE_128B(
                        (uint32_t)((warp_m + mt * 16 + a_row) * 128 + (ks * 16 + a_koff) * 2));
                    LDMATRIX_X4(a[mt][0], a[mt][1], a[mt][2], a[mt][3], aBase + off);
                }
#pragma unroll
                for (int mt = 0; mt < 4; mt++)
#pragma unroll
                    for (int nt = 0; nt < 4; nt++) {
                        int np = nt >> 1, hf = nt & 1;
                        MMA_BF16(acc[mt][nt][0], acc[mt][nt][1], acc[mt][nt][2], acc[mt][nt][3],
                                 a[mt][0], a[mt][1], a[mt][2], a[mt][3],
                                 bh[np][hf * 2], bh[np][hf * 2 + 1]);
                        MMA_BF16(acc[mt][nt][0], acc[mt][nt][1], acc[mt][nt][2], acc[mt][nt][3],
                                 a[mt][0], a[mt][1], a[mt][2], a[mt][3],
                                 blo[np][hf * 2], blo[np][hf * 2 + 1]);
                    }
#pragma unroll
                for (int mt = 0; mt < 4; mt++) {
                    uint32_t off = SMEM_SWIZZLE_128B(
                        (uint32_t)((warp_m + mt * 16 + a_row) * 128 + (ks * 16 + a_koff) * 2));
                    LDMATRIX_X4(a[mt][0], a[mt][1], a[mt][2], a[mt][3], aBase + 16384u + off);
                }
#pragma unroll
                for (int mt = 0; mt < 4; mt++)
#pragma unroll
                    for (int nt = 0; nt < 4; nt++) {
                        int np = nt >> 1, hf = nt & 1;
                        MMA_BF16(acc[mt][nt][0], acc[mt][nt][1], acc[mt][nt][2], acc[mt][nt][3],
                                 a[mt][0], a[mt][1], a[mt][2], a[mt][3],
                                 bh[np][hf * 2], bh[np][hf * 2 + 1]);
                    }
            }
            if (c == 0) NB_ARRIVE(4, NBT);   // slot 0 free for chunk3
        }

        // epilogue
        const int gid = lane >> 2;
        const int tig = lane & 3;
#pragma unroll
        for (int mt = 0; mt < 4; mt++) {
            int r_base = row0 + warp_m + mt * 16 + gid;
#pragma unroll
            for (int nt = 0; nt < 4; nt++) {
                int j = warp_n + nt * 8 + tig * 2;
                float b0 = __ldg(&bias[j]), b1 = __ldg(&bias[j + 1]);
                float2 v0, v1;
                v0.x = acc[mt][nt][0] + b0; v0.y = acc[mt][nt][1] + b1;
                v1.x = acc[mt][nt][2] + b0; v1.y = acc[mt][nt][3] + b1;
                if (relu) {
                    v0.x = fmaxf(v0.x, 0.f); v0.y = fmaxf(v0.y, 0.f);
                    v1.x = fmaxf(v1.x, 0.f); v1.y = fmaxf(v1.y, 0.f);
                }
                if (r_base < N_NODES)
                    *reinterpret_cast<float2*>(out + (size_t)r_base * D + j) = v0;
                if (r_base + 8 < N_NODES)
                    *reinterpret_cast<float2*>(out + (size_t)(r_base + 8) * D + j) = v1;
            }
        }
    }
}

// ---------------- launch ----------------
extern "C" void kernel_launch(void* const* d_in, const int* in_sizes, int n_in,
                              void* d_out, int out_size) {
    const float* x   = (const float*)d_in[0];
    const int*   e32 = (const int*)d_in[1];
    WPtrs wp;
    const float* bl[4];
    for (int l = 0; l < 4; l++) {
        wp.wl[l] = (const float*)d_in[2 + 3 * l];
        bl[l]    = (const float*)d_in[3 + 3 * l];
        wp.wr[l] = (const float*)d_in[4 + 3 * l];
    }
    float* out = (float*)d_out;

    float* h0 = nullptr; float* h1 = nullptr;
    cudaGetSymbolAddress((void**)&h0, g_h0);
    cudaGetSymbolAddress((void**)&h1, g_h1);

    cudaFuncSetAttribute(fused_layer_kernel,
                         cudaFuncAttributeMaxDynamicSharedMemorySize, SMEM_TOT);

    zero_deg_kernel<<<(N_NODES + 255) / 256, 256>>>();
    detect_kernel<<<1, 32>>>(e32);
    decode_count_kernel<<<(2 * N_EDGES + 255) / 256, 256>>>(e32);
    scan1_kernel<<<SCAN_BLOCKS, 1024>>>();
    scan2_kernel<<<1, 64>>>();
    scan3_kernel<<<SCAN_BLOCKS, 1024>>>();
    fill_kernel<<<(N_EDGES + 255) / 256, 256>>>();
    buildWb_kernel<<<(4 * D * K2 + 255) / 256, 256>>>(wp);

    const float* hin[4]  = {x,  h0, h1, h0};
    float*       hout[4] = {h0, h1, h0, out};

    const int layer_blocks = (N_NODES + 127) / 128;   // 391

    for (int l = 0; l < 4; l++)
        fused_layer_kernel<<<layer_blocks, 512, SMEM_TOT>>>(hin[l], l, bl[l], hout[l],
                                                            l == 0 ? 1 : 0);
}

// round 17
// speedup vs baseline: 1.1669x; 1.1669x over previous
#include <cuda_runtime.h>
#include <cuda_bf16.h>
#include <cuda_fp16.h>
#include <cstdint>

#define N_NODES 50000
#define N_EDGES 800000
#define D 128
#define K2 256
#define SCAN_BLOCKS 49   // ceil(50000/1024)

// ---------------- scratch (no allocations allowed) ----------------
__device__ __align__(16) float  g_h0 [N_NODES * D];
__device__ __align__(16) float  g_h1 [N_NODES * D];
__device__ __align__(16) __half g_x16 [N_NODES * D];
__device__ __align__(16) __half g_h016[N_NODES * D];
__device__ __align__(16) __half g_h116[N_NODES * D];
__device__ __align__(16) __nv_bfloat16 g_Wbh[4][D * K2]; // [j][k] K-major, hi
__device__ __align__(16) __nv_bfloat16 g_Wbl[4][D * K2]; // lo
__device__ int   g_deg[N_NODES];
__device__ int   g_rowptr[N_NODES + 1];
__device__ int   g_cursor[N_NODES];
__device__ int   g_eid[N_EDGES];
__device__ int   g_es[N_EDGES];
__device__ int   g_ed[N_EDGES];
__device__ int   g_bsum[SCAN_BLOCKS];
__device__ int   g_is64;

// ---------------- helpers ----------------
__device__ __forceinline__ uint32_t smem_to_u32(const void* p) {
    uint32_t a;
    asm("{ .reg .u64 t; cvta.to.shared.u64 t, %1; cvt.u32.u64 %0, t; }" : "=r"(a) : "l"(p));
    return a;
}
#define SMEM_SWIZZLE_128B(o) ((o) ^ (((o) >> 3) & 0x70))

#define LDMATRIX_X4(r0, r1, r2, r3, addr) \
    asm volatile("ldmatrix.sync.aligned.m8n8.x4.shared.b16 {%0,%1,%2,%3}, [%4];" \
                 : "=r"(r0), "=r"(r1), "=r"(r2), "=r"(r3) : "r"(addr))

#define MMA_BF16(d0, d1, d2, d3, a0, a1, a2, a3, b0, b1) \
    asm volatile("mma.sync.aligned.m16n8k16.row.col.f32.bf16.bf16.f32 " \
                 "{%0,%1,%2,%3}, {%4,%5,%6,%7}, {%8,%9}, {%0,%1,%2,%3};" \
                 : "+f"(d0), "+f"(d1), "+f"(d2), "+f"(d3) \
                 : "r"(a0), "r"(a1), "r"(a2), "r"(a3), "r"(b0), "r"(b1))

__device__ __forceinline__ uint2 pack_hi(float4 v) {
    __nv_bfloat16 h0 = __float2bfloat16(v.x), h1 = __float2bfloat16(v.y);
    __nv_bfloat16 h2 = __float2bfloat16(v.z), h3 = __float2bfloat16(v.w);
    uint2 p;
    p.x = ((uint32_t)__bfloat16_as_ushort(h1) << 16) | __bfloat16_as_ushort(h0);
    p.y = ((uint32_t)__bfloat16_as_ushort(h3) << 16) | __bfloat16_as_ushort(h2);
    return p;
}
__device__ __forceinline__ uint2 pack_lo(float4 v) {
    __nv_bfloat16 h0 = __float2bfloat16(v.x), h1 = __float2bfloat16(v.y);
    __nv_bfloat16 h2 = __float2bfloat16(v.z), h3 = __float2bfloat16(v.w);
    __nv_bfloat16 l0 = __float2bfloat16(v.x - __bfloat162float(h0));
    __nv_bfloat16 l1 = __float2bfloat16(v.y - __bfloat162float(h1));
    __nv_bfloat16 l2 = __float2bfloat16(v.z - __bfloat162float(h2));
    __nv_bfloat16 l3 = __float2bfloat16(v.w - __bfloat162float(h3));
    uint2 p;
    p.x = ((uint32_t)__bfloat16_as_ushort(l1) << 16) | __bfloat16_as_ushort(l0);
    p.y = ((uint32_t)__bfloat16_as_ushort(l3) << 16) | __bfloat16_as_ushort(l2);
    return p;
}

// ---------------- setup kernels ----------------
__global__ void detect_kernel(const int* __restrict__ e32) {
    bool z = (e32[2 * threadIdx.x + 1] == 0);
    unsigned m = __ballot_sync(0xffffffffu, z);
    if (threadIdx.x == 0) g_is64 = (m == 0xffffffffu) ? 1 : 0;
}

__global__ void zero_deg_kernel() {
    int i = blockIdx.x * blockDim.x + threadIdx.x;
    if (i < N_NODES) g_deg[i] = 0;
}

__global__ void decode_count_kernel(const int* __restrict__ e32) {
    int i = blockIdx.x * blockDim.x + threadIdx.x;
    if (i >= 2 * N_EDGES) return;
    int v = g_is64 ? e32[2 * i] : e32[i];
    v = min(max(v, 0), N_NODES - 1);
    if (i < N_EDGES) {
        g_es[i] = v;
    } else {
        g_ed[i - N_EDGES] = v;
        atomicAdd(&g_deg[v], 1);
    }
}

__global__ void x16_kernel(const float* __restrict__ x) {
    int i = blockIdx.x * blockDim.x + threadIdx.x;
    if (i < N_NODES * D / 2) {
        float2 v = reinterpret_cast<const float2*>(x)[i];
        reinterpret_cast<__half2*>(g_x16)[i] = __float22half2_rn(v);
    }
}

__global__ void scan1_kernel() {
    __shared__ int wsum[32];
    int i = blockIdx.x * 1024 + threadIdx.x;
    int lane = threadIdx.x & 31, wrp = threadIdx.x >> 5;
    int v = (i < N_NODES) ? g_deg[i] : 0;
    int x = v;
#pragma unroll
    for (int off = 1; off < 32; off <<= 1) {
        int y = __shfl_up_sync(0xffffffffu, x, off);
        if (lane >= off) x += y;
    }
    if (lane == 31) wsum[wrp] = x;
    __syncthreads();
    if (wrp == 0) {
        int s = wsum[lane];
#pragma unroll
        for (int off = 1; off < 32; off <<= 1) {
            int y = __shfl_up_sync(0xffffffffu, s, off);
            if (lane >= off) s += y;
        }
        wsum[lane] = s;
    }
    __syncthreads();
    int incl = x + (wrp > 0 ? wsum[wrp - 1] : 0);
    if (i < N_NODES) g_rowptr[i] = incl - v;
    if (threadIdx.x == 1023) g_bsum[blockIdx.x] = incl;
}

__global__ void scan2_kernel() {
    __shared__ int ws[2];
    int t = threadIdx.x;
    int lane = t & 31, wrp = t >> 5;
    int v = (t < SCAN_BLOCKS) ? g_bsum[t] : 0;
    int x = v;
#pragma unroll
    for (int off = 1; off < 32; off <<= 1) {
        int y = __shfl_up_sync(0xffffffffu, x, off);
        if (lane >= off) x += y;
    }
    if (lane == 31) ws[wrp] = x;
    __syncthreads();
    int excl = x - v + (wrp == 1 ? ws[0] : 0);
    if (t < SCAN_BLOCKS) g_bsum[t] = excl;
}

__global__ void scan3_kernel() {
    int i = blockIdx.x * 1024 + threadIdx.x;
    if (i < N_NODES) {
        int v = g_rowptr[i] + g_bsum[blockIdx.x];
        g_rowptr[i] = v;
        g_cursor[i] = v;
    }
    if (i == 0) g_rowptr[N_NODES] = N_EDGES;
}

__global__ void fill_kernel() {
    int e = blockIdx.x * blockDim.x + threadIdx.x;
    if (e < N_EDGES) {
        int pos = atomicAdd(&g_cursor[g_ed[e]], 1);
        g_eid[pos] = g_es[e];
    }
}

struct WPtrs { const float* wl[4]; const float* wr[4]; };
__global__ void buildWb_kernel(WPtrs wp) {
    int idx = blockIdx.x * blockDim.x + threadIdx.x;
    if (idx < 4 * D * K2) {
        int layer = idx >> 15;
        int rem = idx & 32767;
        int j = rem >> 8;
        int k = rem & 255;
        float w = (k < D) ? wp.wl[layer][j * D + k] : wp.wr[layer][j * D + (k - D)];
        __nv_bfloat16 hi = __float2bfloat16(w);
        __nv_bfloat16 lo = __float2bfloat16(w - __bfloat162float(hi));
        g_Wbh[layer][rem] = hi;
        g_Wbl[layer][rem] = lo;
    }
}

// ---------------- fused layer (R13 structure, fp16 gather) -------------------
// smem: A 64KB (AH0@0, AL0@16K, AH1@32K, AL1@48K; chunks 2/3 reuse 0/16K)
//       B 32KB (BH@64K, BL@80K). Total 96KB -> occupancy 2.
#define OFF_BH 65536
#define OFF_BL 81920
#define SMEM_TOT 98304

__global__ void __launch_bounds__(256, 2)
fused_layer_kernel(const float* __restrict__ hin, const __half* __restrict__ hin16,
                   int layer, const float* __restrict__ bias,
                   float* __restrict__ out, __half* __restrict__ out16, int relu) {
    extern __shared__ char smem[];
    const uint32_t smem_base = smem_to_u32(smem);
    const int tid  = threadIdx.x;
    const int wid  = tid >> 5;
    const int lane = tid & 31;
    const int row0 = blockIdx.x * 128;
    const int warp_m = (wid >> 2) * 64;
    const int warp_n = (wid & 3) * 32;

    const __nv_bfloat16* __restrict__ Bhp = g_Wbh[layer];
    const __nv_bfloat16* __restrict__ Blp = g_Wbl[layer];

    // ---- phase 1: gather means (fp16 reads) into A smem chunks 0,1 ----
    for (int nn = 0; nn < 16; nn++) {
        int r = wid * 16 + nn;
        int node = row0 + r;
        float4 acc = make_float4(0.f, 0.f, 0.f, 0.f);
        if (node < N_NODES) {
            int beg = g_rowptr[node];
            int end = g_rowptr[node + 1];
            int i = beg;
            for (; i + 7 < end; i += 8) {
                uint2 u[8];
#pragma unroll
                for (int q = 0; q < 8; q++) {
                    int s = __ldg(&g_eid[i + q]);
                    u[q] = *reinterpret_cast<const uint2*>(hin16 + (size_t)s * D + lane * 4);
                }
#pragma unroll
                for (int q = 0; q < 8; q++) {
                    float2 f0 = __half22float2(*reinterpret_cast<const __half2*>(&u[q].x));
                    float2 f1 = __half22float2(*reinterpret_cast<const __half2*>(&u[q].y));
                    acc.x += f0.x; acc.y += f0.y; acc.z += f1.x; acc.w += f1.y;
                }
            }
            for (; i < end; i++) {
                int s = __ldg(&g_eid[i]);
                uint2 u = *reinterpret_cast<const uint2*>(hin16 + (size_t)s * D + lane * 4);
                float2 f0 = __half22float2(*reinterpret_cast<const __half2*>(&u.x));
                float2 f1 = __half22float2(*reinterpret_cast<const __half2*>(&u.y));
                acc.x += f0.x; acc.y += f0.y; acc.z += f1.x; acc.w += f1.y;
            }
            float inv = 1.0f / (float)max(end - beg, 1);
            acc.x *= inv; acc.y *= inv; acc.z *= inv; acc.w *= inv;
        }
        uint32_t cs = (uint32_t)(lane >> 4) * 32768u;
        uint32_t sw = SMEM_SWIZZLE_128B((uint32_t)(r * 128 + (lane & 15) * 8));
        *reinterpret_cast<uint2*>(smem + cs + sw)         = pack_hi(acc);
        *reinterpret_cast<uint2*>(smem + cs + 16384 + sw) = pack_lo(acc);
    }

    // ---- phase 2: HMMA over 4 K-chunks ----
    float acc[4][4][4];
#pragma unroll
    for (int mt = 0; mt < 4; mt++)
#pragma unroll
        for (int nt = 0; nt < 4; nt++)
#pragma unroll
            for (int q = 0; q < 4; q++) acc[mt][nt][q] = 0.f;

    const int a_row  = (lane & 15);
    const int a_koff = (lane >> 4) * 8;
    const int b_row  = (lane & 7) + ((lane >> 4) << 3);
    const int b_koff = ((lane >> 3) & 1) * 8;

    for (int chunk = 0; chunk < 4; chunk++) {
#pragma unroll
        for (int i = 0; i < 8; i++) {
            int g  = tid + i * 256;
            int r  = g >> 4;
            int c4 = g & 15;
            int k = chunk * 64 + c4 * 4;
            uint2 vh = *reinterpret_cast<const uint2*>(Bhp + (size_t)r * K2 + k);
            uint2 vl = *reinterpret_cast<const uint2*>(Blp + (size_t)r * K2 + k);
            uint32_t sw = SMEM_SWIZZLE_128B((uint32_t)(r * 128 + c4 * 8));
            *reinterpret_cast<uint2*>(smem + OFF_BH + sw) = vh;
            *reinterpret_cast<uint2*>(smem + OFF_BL + sw) = vl;
        }
        if (chunk >= 2) {
#pragma unroll
            for (int i = 0; i < 8; i++) {
                int g  = tid + i * 256;
                int r  = g >> 4;
                int c4 = g & 15;
                int grow = row0 + r;
                int k2 = (chunk - 2) * 64 + c4 * 4;
                float4 v = make_float4(0.f, 0.f, 0.f, 0.f);
                if (grow < N_NODES)
                    v = *reinterpret_cast<const float4*>(hin + (size_t)grow * D + k2);
                uint32_t sw = SMEM_SWIZZLE_128B((uint32_t)(r * 128 + c4 * 8));
                *reinterpret_cast<uint2*>(smem + sw)         = pack_hi(v);
                *reinterpret_cast<uint2*>(smem + 16384 + sw) = pack_lo(v);
            }
        }
        __syncthreads();

        const uint32_t offAH = (chunk == 1) ? 32768u : 0u;
        const uint32_t offAL = offAH + 16384u;

#pragma unroll
        for (int ks = 0; ks < 4; ks++) {
            uint32_t bh[2][4], blo[2][4];
#pragma unroll
            for (int np = 0; np < 2; np++) {
                uint32_t off = SMEM_SWIZZLE_128B(
                    (uint32_t)((warp_n + np * 16 + b_row) * 128 + (ks * 16 + b_koff) * 2));
                LDMATRIX_X4(bh[np][0], bh[np][1], bh[np][2], bh[np][3],
                            smem_base + OFF_BH + off);
                LDMATRIX_X4(blo[np][0], blo[np][1], blo[np][2], blo[np][3],
                            smem_base + OFF_BL + off);
            }
            uint32_t a[4][4];
#pragma unroll
            for (int mt = 0; mt < 4; mt++) {
                uint32_t off = SMEM_SWIZZLE_128B(
                    (uint32_t)((warp_m + mt * 16 + a_row) * 128 + (ks * 16 + a_koff) * 2));
                LDMATRIX_X4(a[mt][0], a[mt][1], a[mt][2], a[mt][3],
                            smem_base + offAH + off);
            }
#pragma unroll
            for (int mt = 0; mt < 4; mt++)
#pragma unroll
                for (int nt = 0; nt < 4; nt++) {
                    int np = nt >> 1, hf = nt & 1;
                    MMA_BF16(acc[mt][nt][0], acc[mt][nt][1], acc[mt][nt][2], acc[mt][nt][3],
                             a[mt][0], a[mt][1], a[mt][2], a[mt][3],
                             bh[np][hf * 2], bh[np][hf * 2 + 1]);
                    MMA_BF16(acc[mt][nt][0], acc[mt][nt][1], acc[mt][nt][2], acc[mt][nt][3],
                             a[mt][0], a[mt][1], a[mt][2], a[mt][3],
                             blo[np][hf * 2], blo[np][hf * 2 + 1]);
                }
#pragma unroll
            for (int mt = 0; mt < 4; mt++) {
                uint32_t off = SMEM_SWIZZLE_128B(
                    (uint32_t)((warp_m + mt * 16 + a_row) * 128 + (ks * 16 + a_koff) * 2));
                LDMATRIX_X4(a[mt][0], a[mt][1], a[mt][2], a[mt][3],
                            smem_base + offAL + off);
            }
#pragma unroll
            for (int mt = 0; mt < 4; mt++)
#pragma unroll
                for (int nt = 0; nt < 4; nt++) {
                    int np = nt >> 1, hf = nt & 1;
                    MMA_BF16(acc[mt][nt][0], acc[mt][nt][1], acc[mt][nt][2], acc[mt][nt][3],
                             a[mt][0], a[mt][1], a[mt][2], a[mt][3],
                             bh[np][hf * 2], bh[np][hf * 2 + 1]);
                }
        }
        __syncthreads();
    }

    // ---- epilogue: bias (+relu), store fp32 + fp16 shadow ----
    const int gid = lane >> 2;
    const int tig = lane & 3;
#pragma unroll
    for (int mt = 0; mt < 4; mt++) {
        int r_base = row0 + warp_m + mt * 16 + gid;
#pragma unroll
        for (int nt = 0; nt < 4; nt++) {
            int j = warp_n + nt * 8 + tig * 2;
            float b0 = __ldg(&bias[j]), b1 = __ldg(&bias[j + 1]);
            float2 v0, v1;
            v0.x = acc[mt][nt][0] + b0; v0.y = acc[mt][nt][1] + b1;
            v1.x = acc[mt][nt][2] + b0; v1.y = acc[mt][nt][3] + b1;
            if (relu) {
                v0.x = fmaxf(v0.x, 0.f); v0.y = fmaxf(v0.y, 0.f);
                v1.x = fmaxf(v1.x, 0.f); v1.y = fmaxf(v1.y, 0.f);
            }
            if (r_base < N_NODES) {
                *reinterpret_cast<float2*>(out + (size_t)r_base * D + j) = v0;
                if (out16)
                    *reinterpret_cast<__half2*>(out16 + (size_t)r_base * D + j) =
                        __float22half2_rn(v0);
            }
            if (r_base + 8 < N_NODES) {
                *reinterpret_cast<float2*>(out + (size_t)(r_base + 8) * D + j) = v1;
                if (out16)
                    *reinterpret_cast<__half2*>(out16 + (size_t)(r_base + 8) * D + j) =
                        __float22half2_rn(v1);
            }
        }
    }
}

// ---------------- launch ----------------
extern "C" void kernel_launch(void* const* d_in, const int* in_sizes, int n_in,
                              void* d_out, int out_size) {
    const float* x   = (const float*)d_in[0];
    const int*   e32 = (const int*)d_in[1];
    WPtrs wp;
    const float* bl[4];
    for (int l = 0; l < 4; l++) {
        wp.wl[l] = (const float*)d_in[2 + 3 * l];
        bl[l]    = (const float*)d_in[3 + 3 * l];
        wp.wr[l] = (const float*)d_in[4 + 3 * l];
    }
    float* out = (float*)d_out;

    float *h0, *h1; __half *x16, *h016, *h116;
    cudaGetSymbolAddress((void**)&h0,  g_h0);
    cudaGetSymbolAddress((void**)&h1,  g_h1);
    cudaGetSymbolAddress((void**)&x16, g_x16);
    cudaGetSymbolAddress((void**)&h016, g_h016);
    cudaGetSymbolAddress((void**)&h116, g_h116);

    cudaFuncSetAttribute(fused_layer_kernel,
                         cudaFuncAttributeMaxDynamicSharedMemorySize, SMEM_TOT);

    zero_deg_kernel<<<(N_NODES + 255) / 256, 256>>>();
    detect_kernel<<<1, 32>>>(e32);
    decode_count_kernel<<<(2 * N_EDGES + 255) / 256, 256>>>(e32);
    x16_kernel<<<(N_NODES * D / 2 + 255) / 256, 256>>>(x);
    scan1_kernel<<<SCAN_BLOCKS, 1024>>>();
    scan2_kernel<<<1, 64>>>();
    scan3_kernel<<<SCAN_BLOCKS, 1024>>>();
    fill_kernel<<<(N_EDGES + 255) / 256, 256>>>();
    buildWb_kernel<<<(4 * D * K2 + 255) / 256, 256>>>(wp);

    const float*  hin [4] = {x,   h0,   h1,   h0};
    const __half* hin16[4] = {x16, h016, h116, h016};
    float*        hout[4] = {h0,  h1,   h0,   out};
    __half*       hout16[4] = {h016, h116, h016, nullptr};

    const int layer_blocks = (N_NODES + 127) / 128;   // 391

    for (int l = 0; l < 4; l++)
        fused_layer_kernel<<<layer_blocks, 256, SMEM_TOT>>>(
            hin[l], hin16[l], l, bl[l], hout[l], hout16[l], l == 0 ? 1 : 0);
}